// round 3
// baseline (speedup 1.0000x reference)
#include <cuda_runtime.h>
#include <cuda_bf16.h>

#define N_MOLS   2048
#define N_NODES  51200
#define N_EDGES  102400
#define MAX_NB   6
#define HIDDEN   300
#define NODE_FDIM 133
#define EDGE_FDIM 147
#define DEPTH    6
#define H4       (HIDDEN / 4)   // 75 float4 per row

// ---------------- scratch (static device globals; allocation-free) ----------
__device__ float g_inp[N_EDGES * HIDDEN];   // pre-activation edge features
__device__ float g_msg[N_EDGES * HIDDEN];   // current messages
__device__ float g_G  [N_EDGES * HIDDEN];   // message @ W_h
__device__ float g_S  [N_NODES * HIDDEN];   // per-node neighbor sums
__device__ int   g_cnt[N_MOLS];

// Which buffer a GEMM reads/writes (so kernels reference globals directly,
// no host-side device pointers needed).
//  A-source: 0 = g_msg, 1 = external A1 only, 2 = concat(f_nodes, g_S)
//  C-dest : 0 = g_G, 1 = g_inp(+g_msg relu), 2 = atomic segment-sum to out

// ---------------- SGEMM: C[M,N] = A[M,K] @ B[K,N] ---------------------------
template<int MODE>   // 0: G = msg@W_h   1: inp/msg = f_edges@W_i   2: out GEMM
__launch_bounds__(256)
__global__ void sgemm_k(const float* __restrict__ A1,   // external A (mode 1,2)
                        const float* __restrict__ B,
                        const float* __restrict__ bias,  // mode 2
                        const int*  __restrict__ molids, // mode 2
                        float* __restrict__ out)         // mode 2
{
    // Per-mode compile-time shapes
    const int K1 = (MODE == 0) ? HIDDEN : (MODE == 1) ? EDGE_FDIM : NODE_FDIM;
    const int K  = (MODE == 2) ? (NODE_FDIM + HIDDEN) : K1;
    const int N  = HIDDEN;

    __shared__ float As[16][132];   // transposed A tile, padded
    __shared__ float Bs[16][64];

    const int t  = threadIdx.x;
    const int tx = t & 15;          // 16 col-groups * 4 cols  = 64
    const int ty = t >> 4;          // 16 row-groups * 8 rows  = 128
    const int m0 = blockIdx.y * 128;
    const int n0 = blockIdx.x * 64;

    float acc[8][4] = {};

    for (int k0 = 0; k0 < K; k0 += 16) {
        // load A tile, transposed into As[k][m]; coalesced along k
        #pragma unroll
        for (int i = 0; i < 8; i++) {
            const int k  = t & 15;
            const int m  = (t >> 4) + i * 16;
            const int gk = k0 + k;
            float v = 0.f;
            if (gk < K) {
                const int gm = m0 + m;
                if (MODE == 0) {
                    v = g_msg[gm * HIDDEN + gk];
                } else if (MODE == 1) {
                    v = A1[gm * EDGE_FDIM + gk];
                } else {
                    v = (gk < NODE_FDIM) ? A1[gm * NODE_FDIM + gk]
                                         : g_S[gm * HIDDEN + (gk - NODE_FDIM)];
                }
            }
            As[k][m] = v;
        }
        // load B tile; coalesced along n
        #pragma unroll
        for (int i = 0; i < 4; i++) {
            const int k  = (t >> 6) + i * 4;
            const int n  = t & 63;
            const int gk = k0 + k;
            const int gn = n0 + n;
            Bs[k][n] = (gk < K && gn < N) ? B[gk * N + gn] : 0.f;
        }
        __syncthreads();

        #pragma unroll
        for (int kk = 0; kk < 16; kk++) {
            const float4 a0 = *(const float4*)&As[kk][ty * 8];
            const float4 a1 = *(const float4*)&As[kk][ty * 8 + 4];
            const float4 b  = *(const float4*)&Bs[kk][tx * 4];
            const float av[8] = {a0.x,a0.y,a0.z,a0.w,a1.x,a1.y,a1.z,a1.w};
            const float bv[4] = {b.x,b.y,b.z,b.w};
            #pragma unroll
            for (int i = 0; i < 8; i++)
                #pragma unroll
                for (int j = 0; j < 4; j++)
                    acc[i][j] = fmaf(av[i], bv[j], acc[i][j]);
        }
        __syncthreads();
    }

    #pragma unroll
    for (int i = 0; i < 8; i++) {
        const int gm = m0 + ty * 8 + i;
        int molid = 0;
        if (MODE == 2) molid = molids[gm];
        #pragma unroll
        for (int j = 0; j < 4; j++) {
            const int gn = n0 + tx * 4 + j;
            if (gn < N) {
                const float v = acc[i][j];
                if (MODE == 0) {
                    g_G[gm * N + gn] = v;
                } else if (MODE == 1) {
                    g_inp[gm * N + gn] = v;
                    g_msg[gm * N + gn] = fmaxf(v, 0.f);
                } else {
                    const float h = fmaxf(v + bias[gn], 0.f);
                    atomicAdd(&out[molid * HIDDEN + gn], h);
                }
            }
        }
    }
}

// ---------------- S[v] = sum_{k<6} X[n2e[v,k]]  (float4 per thread) ---------
// SRC 0: read g_G, SRC 1: read g_msg
template<int SRC>
__global__ void node_agg_k(const int* __restrict__ n2e)
{
    const int idx = blockIdx.x * blockDim.x + threadIdx.x;
    if (idx >= N_NODES * H4) return;
    const int v = idx / H4;
    const int c = idx - v * H4;
    const float4* X4 = (SRC == 0) ? (const float4*)g_G : (const float4*)g_msg;
    float4 s = make_float4(0.f, 0.f, 0.f, 0.f);
    #pragma unroll
    for (int k = 0; k < MAX_NB; k++) {
        const int e = __ldg(&n2e[v * MAX_NB + k]);
        const float4 g = __ldg(&X4[e * H4 + c]);
        s.x += g.x; s.y += g.y; s.z += g.z; s.w += g.w;
    }
    ((float4*)g_S)[idx] = s;
}

// ------------- msg[e] = relu(inp[e] + S[e2n[e]] - G[rev[e]]) ----------------
__global__ void edge_update_k(const int* __restrict__ e2n,
                              const int* __restrict__ e2rev)
{
    const int idx = blockIdx.x * blockDim.x + threadIdx.x;
    if (idx >= N_EDGES * H4) return;
    const int e = idx / H4;
    const int c = idx - e * H4;
    const int v   = __ldg(&e2n[e]);
    const int rev = __ldg(&e2rev[e]);
    const float4 pi = ((const float4*)g_inp)[idx];
    const float4 ps = __ldg(&((const float4*)g_S)[v * H4 + c]);
    const float4 pg = __ldg(&((const float4*)g_G)[rev * H4 + c]);
    float4 m;
    m.x = fmaxf(pi.x + ps.x - pg.x, 0.f);
    m.y = fmaxf(pi.y + ps.y - pg.y, 0.f);
    m.z = fmaxf(pi.z + ps.z - pg.z, 0.f);
    m.w = fmaxf(pi.w + ps.w - pg.w, 0.f);
    ((float4*)g_msg)[idx] = m;
}

// ---------------- init: zero out + counts, then count -----------------------
__global__ void zero_out_k(float* __restrict__ out)
{
    const int i = blockIdx.x * blockDim.x + threadIdx.x;
    if (i < N_MOLS * HIDDEN) out[i] = 0.f;
    if (i < N_MOLS) g_cnt[i] = 0;
}

__global__ void count_k(const int* __restrict__ mol_ids)
{
    const int v = blockIdx.x * blockDim.x + threadIdx.x;
    if (v < N_NODES) atomicAdd(&g_cnt[mol_ids[v]], 1);
}

__global__ void divide_k(float* __restrict__ out)
{
    const int i = blockIdx.x * blockDim.x + threadIdx.x;
    if (i >= N_MOLS * HIDDEN) return;
    const int m = i / HIDDEN;
    const int c = g_cnt[m];
    out[i] = (c > 0) ? out[i] / (float)c : 0.f;
}

// ---------------------------------------------------------------------------
extern "C" void kernel_launch(void* const* d_in, const int* in_sizes, int n_in,
                              void* d_out, int out_size)
{
    const float* f_nodes = (const float*)d_in[0];
    const float* f_edges = (const float*)d_in[1];
    const float* W_i     = (const float*)d_in[2];
    const float* W_h     = (const float*)d_in[3];
    const float* W_o     = (const float*)d_in[4];
    const float* b_o     = (const float*)d_in[5];
    const int*   n2e     = (const int*)d_in[6];
    const int*   e2n     = (const int*)d_in[7];
    const int*   e2rev   = (const int*)d_in[8];
    const int*   mol_ids = (const int*)d_in[9];
    float* out = (float*)d_out;

    // zero output accumulator + mol counts (pure kernel, no memset API)
    zero_out_k<<<(N_MOLS * HIDDEN + 255) / 256, 256>>>(out);
    count_k<<<(N_NODES + 255) / 256, 256>>>(mol_ids);

    const dim3 gridE((HIDDEN + 63) / 64, N_EDGES / 128);
    const dim3 gridN((HIDDEN + 63) / 64, N_NODES / 128);

    // inp = f_edges @ W_i ; msg = relu(inp)
    sgemm_k<1><<<gridE, 256>>>(f_edges, W_i, nullptr, nullptr, nullptr);

    const int aggBlocks  = (N_NODES * H4 + 255) / 256;
    const int edgeBlocks = (N_EDGES * H4 + 255) / 256;

    for (int it = 0; it < DEPTH - 1; it++) {
        // G = msg @ W_h
        sgemm_k<0><<<gridE, 256>>>(nullptr, W_h, nullptr, nullptr, nullptr);
        // S[v] = sum_k G[n2e[v,k]]
        node_agg_k<0><<<aggBlocks, 256>>>(n2e);
        // msg[e] = relu(inp[e] + S[e2n[e]] - G[rev[e]])
        edge_update_k<<<edgeBlocks, 256>>>(e2n, e2rev);
    }

    // final neighbor sum of messages into S
    node_agg_k<1><<<aggBlocks, 256>>>(n2e);

    // node_hiddens = relu([f_nodes, S] @ W_o + b_o); atomic segment-sum to out
    sgemm_k<2><<<gridN, 256>>>(f_nodes, W_o, b_o, mol_ids, out);

    // mean
    divide_k<<<(N_MOLS * HIDDEN + 255) / 256, 256>>>(out);
}

// round 6
// speedup vs baseline: 1.0027x; 1.0027x over previous
#include <cuda_runtime.h>
#include <cuda_bf16.h>
#include <cstdint>

#define N_MOLS   2048
#define N_NODES  51200
#define N_EDGES  102400
#define MAX_NB   6
#define HIDDEN   300
#define NODE_FDIM 133
#define EDGE_FDIM 147
#define DEPTH    6
#define H4       (HIDDEN / 4)   // 75 float4 per row

// ---------------- scratch (static device globals; allocation-free) ----------
__device__ float g_inp [N_EDGES * HIDDEN];   // pre-activation edge features
__device__ float g_msgh[N_EDGES * HIDDEN];   // message hi (tf32-exact)
__device__ float g_msgl[N_EDGES * HIDDEN];   // message lo (tf32-exact residual)
__device__ float g_G   [N_EDGES * HIDDEN];   // message @ W_h
__device__ float g_S   [N_NODES * HIDDEN];   // per-node neighbor sums
__device__ float g_Whh [HIDDEN * HIDDEN];    // W_h hi
__device__ float g_Whl [HIDDEN * HIDDEN];    // W_h lo
__device__ int   g_cnt [N_MOLS];

// ---------------- helpers ----------------------------------------------------
__device__ __forceinline__ float tf32_rn(float x) {
    uint32_t u;
    asm("cvt.rna.tf32.f32 %0, %1;" : "=r"(u) : "f"(x));
    return __uint_as_float(u);
}

__device__ __forceinline__ void mma_tf32(float* d, const uint32_t* a, const uint32_t* b) {
    asm volatile(
        "mma.sync.aligned.m16n8k8.row.col.f32.tf32.tf32.f32 "
        "{%0,%1,%2,%3}, {%4,%5,%6,%7}, {%8,%9}, {%0,%1,%2,%3};\n"
        : "+f"(d[0]), "+f"(d[1]), "+f"(d[2]), "+f"(d[3])
        : "r"(a[0]), "r"(a[1]), "r"(a[2]), "r"(a[3]), "r"(b[0]), "r"(b[1]));
}

// ---------------- tf32 tensor-core GEMM: g_G = msg(hi+lo) @ W_h --------------
// M = N_EDGES, N = K = HIDDEN.  Block tile 128x64, 8 warps of 32x32.
#define BM 128
#define BN 64
#define BK 16
__launch_bounds__(256)
__global__ void mma_gemm_Wh_k()
{
    __shared__ float Ah[BM][BK + 4], Al[BM][BK + 4];   // stride 20: conflict-free frag reads
    __shared__ float Bh[BK][BN + 8], Bl[BK][BN + 8];   // stride 72: conflict-free frag reads

    const int tid  = threadIdx.x;
    const int lane = tid & 31;
    const int wid  = tid >> 5;
    const int wm   = (wid >> 1) * 32;      // warp m offset within block tile (0..96)
    const int wn   = (wid & 1) * 32;       // warp n offset within block tile (0/32)
    const int g    = lane >> 2;            // groupID (0..7)
    const int tg   = lane & 3;             // thread-in-group (0..3)
    const int m0   = blockIdx.y * BM;
    const int n0   = blockIdx.x * BN;

    // hoisted tile-load indices
    const int ar = tid >> 2;               // A row base (0..63), +64 on second pass
    const int af = (tid & 3) * 4;          // A col group
    const int br = tid >> 4;               // B row (0..15)
    const int bf = (tid & 15) * 4;         // B col group

    float d[2][4][4];
    #pragma unroll
    for (int mt = 0; mt < 2; mt++)
        #pragma unroll
        for (int nt = 0; nt < 4; nt++)
            #pragma unroll
            for (int r = 0; r < 4; r++) d[mt][nt][r] = 0.f;

    for (int k0 = 0; k0 < HIDDEN; k0 += BK) {
        // ---- A tile: 128 rows x 16 cols, hi & lo (2 float4 per thread each) ----
        #pragma unroll
        for (int i = 0; i < 2; i++) {
            const int r  = ar + i * 64;
            const int gk = k0 + af;
            float4 vh = make_float4(0.f,0.f,0.f,0.f);
            float4 vl = vh;
            if (gk < HIDDEN) {
                const size_t off = (size_t)(m0 + r) * HIDDEN + gk;
                vh = *(const float4*)&g_msgh[off];
                vl = *(const float4*)&g_msgl[off];
            }
            *(float4*)&Ah[r][af] = vh;
            *(float4*)&Al[r][af] = vl;
        }
        // ---- B tile: 16 rows x 64 cols, hi & lo (1 float4 per thread each) ----
        {
            const int gk = k0 + br;
            const int gn = n0 + bf;
            float4 vh = make_float4(0.f,0.f,0.f,0.f);
            float4 vl = vh;
            if (gk < HIDDEN && gn < HIDDEN) {
                vh = *(const float4*)&g_Whh[gk * HIDDEN + gn];
                vl = *(const float4*)&g_Whl[gk * HIDDEN + gn];
            }
            *(float4*)&Bh[br][bf] = vh;
            *(float4*)&Bl[br][bf] = vl;
        }
        __syncthreads();

        #pragma unroll
        for (int kk = 0; kk < BK; kk += 8) {
            uint32_t ah[2][4], al[2][4], bh[4][2], bl[4][2];
            #pragma unroll
            for (int mt = 0; mt < 2; mt++) {
                const int row = wm + mt * 16;
                ah[mt][0] = __float_as_uint(Ah[row + g    ][kk + tg    ]);
                ah[mt][1] = __float_as_uint(Ah[row + g + 8][kk + tg    ]);
                ah[mt][2] = __float_as_uint(Ah[row + g    ][kk + tg + 4]);
                ah[mt][3] = __float_as_uint(Ah[row + g + 8][kk + tg + 4]);
                al[mt][0] = __float_as_uint(Al[row + g    ][kk + tg    ]);
                al[mt][1] = __float_as_uint(Al[row + g + 8][kk + tg    ]);
                al[mt][2] = __float_as_uint(Al[row + g    ][kk + tg + 4]);
                al[mt][3] = __float_as_uint(Al[row + g + 8][kk + tg + 4]);
            }
            #pragma unroll
            for (int nt = 0; nt < 4; nt++) {
                const int col = wn + nt * 8 + g;
                bh[nt][0] = __float_as_uint(Bh[kk + tg    ][col]);
                bh[nt][1] = __float_as_uint(Bh[kk + tg + 4][col]);
                bl[nt][0] = __float_as_uint(Bl[kk + tg    ][col]);
                bl[nt][1] = __float_as_uint(Bl[kk + tg + 4][col]);
            }
            #pragma unroll
            for (int mt = 0; mt < 2; mt++)
                #pragma unroll
                for (int nt = 0; nt < 4; nt++) {
                    mma_tf32(d[mt][nt], ah[mt], bh[nt]);  // hi*hi
                    mma_tf32(d[mt][nt], ah[mt], bl[nt]);  // hi*lo
                    mma_tf32(d[mt][nt], al[mt], bh[nt]);  // lo*hi
                }
        }
        __syncthreads();
    }

    // ---- epilogue: write g_G ----
    #pragma unroll
    for (int mt = 0; mt < 2; mt++) {
        const int gm = m0 + wm + mt * 16 + g;
        #pragma unroll
        for (int nt = 0; nt < 4; nt++) {
            const int gn = n0 + wn + nt * 8 + 2 * tg;
            if (gn < HIDDEN) {
                *(float2*)&g_G[(size_t)gm * HIDDEN + gn]       = make_float2(d[mt][nt][0], d[mt][nt][1]);
                *(float2*)&g_G[(size_t)(gm + 8) * HIDDEN + gn] = make_float2(d[mt][nt][2], d[mt][nt][3]);
            }
        }
    }
}

// ---------------- split W_h into tf32 hi/lo ---------------------------------
__global__ void split_Wh_k(const float* __restrict__ W_h)
{
    const int i = blockIdx.x * blockDim.x + threadIdx.x;
    if (i >= HIDDEN * HIDDEN) return;
    const float w = W_h[i];
    const float h = tf32_rn(w);
    g_Whh[i] = h;
    g_Whl[i] = tf32_rn(w - h);
}

// ---------------- SIMT SGEMM for modes 1 (W_i) and 2 (W_o) ------------------
template<int MODE>   // 1: inp/msg(hi,lo) = f_edges@W_i   2: out GEMM (atomic seg-sum)
__launch_bounds__(256)
__global__ void sgemm_k(const float* __restrict__ A1,
                        const float* __restrict__ B,
                        const float* __restrict__ bias,
                        const int*  __restrict__ molids,
                        float* __restrict__ out)
{
    const int K1 = (MODE == 1) ? EDGE_FDIM : NODE_FDIM;
    const int K  = (MODE == 2) ? (NODE_FDIM + HIDDEN) : K1;
    const int N  = HIDDEN;

    __shared__ float As[16][132];
    __shared__ float Bs[16][64];

    const int t  = threadIdx.x;
    const int tx = t & 15;
    const int ty = t >> 4;
    const int m0 = blockIdx.y * 128;
    const int n0 = blockIdx.x * 64;

    float acc[8][4] = {};

    for (int k0 = 0; k0 < K; k0 += 16) {
        #pragma unroll
        for (int i = 0; i < 8; i++) {
            const int k  = t & 15;
            const int m  = (t >> 4) + i * 16;
            const int gk = k0 + k;
            float v = 0.f;
            if (gk < K) {
                const int gm = m0 + m;
                if (MODE == 1) {
                    v = A1[gm * EDGE_FDIM + gk];
                } else {
                    v = (gk < NODE_FDIM) ? A1[gm * NODE_FDIM + gk]
                                         : g_S[gm * HIDDEN + (gk - NODE_FDIM)];
                }
            }
            As[k][m] = v;
        }
        #pragma unroll
        for (int i = 0; i < 4; i++) {
            const int k  = (t >> 6) + i * 4;
            const int n  = t & 63;
            const int gk = k0 + k;
            const int gn = n0 + n;
            Bs[k][n] = (gk < K && gn < N) ? B[gk * N + gn] : 0.f;
        }
        __syncthreads();

        #pragma unroll
        for (int kk = 0; kk < 16; kk++) {
            const float4 a0 = *(const float4*)&As[kk][ty * 8];
            const float4 a1 = *(const float4*)&As[kk][ty * 8 + 4];
            const float4 b  = *(const float4*)&Bs[kk][tx * 4];
            const float av[8] = {a0.x,a0.y,a0.z,a0.w,a1.x,a1.y,a1.z,a1.w};
            const float bv[4] = {b.x,b.y,b.z,b.w};
            #pragma unroll
            for (int i = 0; i < 8; i++)
                #pragma unroll
                for (int j = 0; j < 4; j++)
                    acc[i][j] = fmaf(av[i], bv[j], acc[i][j]);
        }
        __syncthreads();
    }

    #pragma unroll
    for (int i = 0; i < 8; i++) {
        const int gm = m0 + ty * 8 + i;
        int molid = 0;
        if (MODE == 2) molid = molids[gm];
        #pragma unroll
        for (int j = 0; j < 4; j++) {
            const int gn = n0 + tx * 4 + j;
            if (gn < N) {
                const float v = acc[i][j];
                if (MODE == 1) {
                    g_inp[gm * N + gn] = v;
                    const float r = fmaxf(v, 0.f);
                    const float h = tf32_rn(r);
                    g_msgh[gm * N + gn] = h;
                    g_msgl[gm * N + gn] = tf32_rn(r - h);
                } else {
                    const float h = fmaxf(v + bias[gn], 0.f);
                    atomicAdd(&out[molid * HIDDEN + gn], h);
                }
            }
        }
    }
}

// ---------------- S[v] = sum_{k<6} X[n2e[v,k]] -------------------------------
// SRC 0: read g_G ;  SRC 1: read g_msgh + g_msgl (final aggregation)
template<int SRC>
__global__ void node_agg_k(const int* __restrict__ n2e)
{
    const int idx = blockIdx.x * blockDim.x + threadIdx.x;
    if (idx >= N_NODES * H4) return;
    const int v = idx / H4;
    const int c = idx - v * H4;
    float4 s = make_float4(0.f, 0.f, 0.f, 0.f);
    #pragma unroll
    for (int k = 0; k < MAX_NB; k++) {
        const int e = __ldg(&n2e[v * MAX_NB + k]);
        if (SRC == 0) {
            const float4 gg = __ldg(&((const float4*)g_G)[e * H4 + c]);
            s.x += gg.x; s.y += gg.y; s.z += gg.z; s.w += gg.w;
        } else {
            const float4 mh = __ldg(&((const float4*)g_msgh)[e * H4 + c]);
            const float4 ml = __ldg(&((const float4*)g_msgl)[e * H4 + c]);
            s.x += mh.x + ml.x; s.y += mh.y + ml.y;
            s.z += mh.z + ml.z; s.w += mh.w + ml.w;
        }
    }
    ((float4*)g_S)[idx] = s;
}

// -------- msg[e] = relu(inp[e] + S[e2n[e]] - G[rev[e]])  (write hi/lo) -------
__global__ void edge_update_k(const int* __restrict__ e2n,
                              const int* __restrict__ e2rev)
{
    const int idx = blockIdx.x * blockDim.x + threadIdx.x;
    if (idx >= N_EDGES * H4) return;
    const int e = idx / H4;
    const int c = idx - e * H4;
    const int v   = __ldg(&e2n[e]);
    const int rev = __ldg(&e2rev[e]);
    const float4 pi = ((const float4*)g_inp)[idx];
    const float4 ps = __ldg(&((const float4*)g_S)[v * H4 + c]);
    const float4 pg = __ldg(&((const float4*)g_G)[rev * H4 + c]);
    float m[4];
    m[0] = fmaxf(pi.x + ps.x - pg.x, 0.f);
    m[1] = fmaxf(pi.y + ps.y - pg.y, 0.f);
    m[2] = fmaxf(pi.z + ps.z - pg.z, 0.f);
    m[3] = fmaxf(pi.w + ps.w - pg.w, 0.f);
    float4 hi, lo;
    hi.x = tf32_rn(m[0]); lo.x = tf32_rn(m[0] - hi.x);
    hi.y = tf32_rn(m[1]); lo.y = tf32_rn(m[1] - hi.y);
    hi.z = tf32_rn(m[2]); lo.z = tf32_rn(m[2] - hi.z);
    hi.w = tf32_rn(m[3]); lo.w = tf32_rn(m[3] - hi.w);
    ((float4*)g_msgh)[idx] = hi;
    ((float4*)g_msgl)[idx] = lo;
}

// ---------------- init / count / divide -------------------------------------
__global__ void zero_out_k(float* __restrict__ out)
{
    const int i = blockIdx.x * blockDim.x + threadIdx.x;
    if (i < N_MOLS * HIDDEN) out[i] = 0.f;
    if (i < N_MOLS) g_cnt[i] = 0;
}

__global__ void count_k(const int* __restrict__ mol_ids)
{
    const int v = blockIdx.x * blockDim.x + threadIdx.x;
    if (v < N_NODES) atomicAdd(&g_cnt[mol_ids[v]], 1);
}

__global__ void divide_k(float* __restrict__ out)
{
    const int i = blockIdx.x * blockDim.x + threadIdx.x;
    if (i >= N_MOLS * HIDDEN) return;
    const int m = i / HIDDEN;
    const int c = g_cnt[m];
    out[i] = (c > 0) ? out[i] / (float)c : 0.f;
}

// ---------------------------------------------------------------------------
extern "C" void kernel_launch(void* const* d_in, const int* in_sizes, int n_in,
                              void* d_out, int out_size)
{
    const float* f_nodes = (const float*)d_in[0];
    const float* f_edges = (const float*)d_in[1];
    const float* W_i     = (const float*)d_in[2];
    const float* W_h     = (const float*)d_in[3];
    const float* W_o     = (const float*)d_in[4];
    const float* b_o     = (const float*)d_in[5];
    const int*   n2e     = (const int*)d_in[6];
    const int*   e2n     = (const int*)d_in[7];
    const int*   e2rev   = (const int*)d_in[8];
    const int*   mol_ids = (const int*)d_in[9];
    float* out = (float*)d_out;

    zero_out_k<<<(N_MOLS * HIDDEN + 255) / 256, 256>>>(out);
    count_k<<<(N_NODES + 255) / 256, 256>>>(mol_ids);
    split_Wh_k<<<(HIDDEN * HIDDEN + 255) / 256, 256>>>(W_h);

    const dim3 gridE((HIDDEN + 63) / 64, N_EDGES / 128);
    const dim3 gridN((HIDDEN + 63) / 64, N_NODES / 128);
    const dim3 gridT((HIDDEN + BN - 1) / BN, N_EDGES / BM);

    // inp = f_edges @ W_i ; msg = relu(inp) (split hi/lo)
    sgemm_k<1><<<gridE, 256>>>(f_edges, W_i, nullptr, nullptr, nullptr);

    const int aggBlocks  = (N_NODES * H4 + 255) / 256;
    const int edgeBlocks = (N_EDGES * H4 + 255) / 256;

    for (int it = 0; it < DEPTH - 1; it++) {
        // G = msg @ W_h  (tf32 tensor cores, 3x split)
        mma_gemm_Wh_k<<<gridT, 256>>>();
        // S[v] = sum_k G[n2e[v,k]]
        node_agg_k<0><<<aggBlocks, 256>>>(n2e);
        // msg[e] = relu(inp[e] + S[e2n[e]] - G[rev[e]]) -> hi/lo
        edge_update_k<<<edgeBlocks, 256>>>(e2n, e2rev);
    }

    // final neighbor sum of messages into S
    node_agg_k<1><<<aggBlocks, 256>>>(n2e);

    // node_hiddens = relu([f_nodes, S] @ W_o + b_o); atomic segment-sum to out
    sgemm_k<2><<<gridN, 256>>>(f_nodes, W_o, b_o, mol_ids, out);

    // mean
    divide_k<<<(N_MOLS * HIDDEN + 255) / 256, 256>>>(out);
}

// round 8
// speedup vs baseline: 1.3544x; 1.3508x over previous
#include <cuda_runtime.h>
#include <cuda_bf16.h>
#include <cstdint>

#define N_MOLS   2048
#define N_NODES  51200
#define N_EDGES  102400
#define MAX_NB   6
#define HIDDEN   300
#define NODE_FDIM 133
#define EDGE_FDIM 147
#define DEPTH    6
#define H4       75      // float4 per 300-col row
#define MPAD     320     // padded K stride for bf16 msg arrays (elems)

// ---------------- scratch (static device globals; allocation-free) ----------
__device__ float g_inp [N_EDGES * HIDDEN];                     // pre-activation edge features
__device__ __align__(16) __nv_bfloat16 g_msgh[N_EDGES * MPAD]; // message hi (bf16), stride 320
__device__ __align__(16) __nv_bfloat16 g_msgl[N_EDGES * MPAD]; // message lo residual
__device__ float g_G   [N_EDGES * HIDDEN];                     // message @ W_h
__device__ float g_S   [N_NODES * HIDDEN];                     // per-node neighbor sums
__device__ __align__(16) __nv_bfloat16 g_Wth[MPAD * MPAD];     // W_h^T hi: [n=320][k=320], zero-padded
__device__ __align__(16) __nv_bfloat16 g_Wtl[MPAD * MPAD];     // W_h^T lo
__device__ int   g_cnt [N_MOLS];

// ---------------- helpers ----------------------------------------------------
__device__ __forceinline__ void bsplit(float x, __nv_bfloat16& h, __nv_bfloat16& l) {
    h = __float2bfloat16(x);
    l = __float2bfloat16(x - __bfloat162float(h));
}

__device__ __forceinline__ void mma_bf16(float* d, const uint32_t* a, const uint32_t* b) {
    asm volatile(
        "mma.sync.aligned.m16n8k16.row.col.f32.bf16.bf16.f32 "
        "{%0,%1,%2,%3}, {%4,%5,%6,%7}, {%8,%9}, {%0,%1,%2,%3};\n"
        : "+f"(d[0]), "+f"(d[1]), "+f"(d[2]), "+f"(d[3])
        : "r"(a[0]), "r"(a[1]), "r"(a[2]), "r"(a[3]), "r"(b[0]), "r"(b[1]));
}

// ---------------- bf16 tensor-core GEMM: g_G = (msg_hi+msg_lo) @ W_h ---------
// Block tile 128x64, 8 warps of 32x32, K looped 10 chunks of 32 (padded 320).
#define BM 128
#define BN 64
#define ASTR 40   // smem row stride in bf16: conflict-free fragment reads
__launch_bounds__(256)
__global__ void mma_gemm_Wh_k()
{
    __shared__ __nv_bfloat16 Ah[BM][ASTR], Al[BM][ASTR];
    __shared__ __nv_bfloat16 Bh[BN][ASTR], Bl[BN][ASTR];

    const int tid  = threadIdx.x;
    const int lane = tid & 31;
    const int wid  = tid >> 5;
    const int wm   = (wid >> 1) * 32;
    const int wn   = (wid & 1) * 32;
    const int g    = lane >> 2;
    const int tg   = lane & 3;
    const int m0   = blockIdx.y * BM;
    const int n0   = blockIdx.x * BN;

    const int arow = tid >> 2;          // 0..63 (+64 on 2nd pass)
    const int acol = (tid & 3) * 8;     // 8 bf16 per uint4

    float d[2][4][4];
    #pragma unroll
    for (int mt = 0; mt < 2; mt++)
        #pragma unroll
        for (int nt = 0; nt < 4; nt++)
            #pragma unroll
            for (int r = 0; r < 4; r++) d[mt][nt][r] = 0.f;

    for (int c = 0; c < 10; c++) {
        const int k0 = c * 32;
        // ---- A tiles: 128 x 32 bf16, hi & lo (uint4 = 8 bf16 per thread x2) --
        #pragma unroll
        for (int i = 0; i < 2; i++) {
            const int r = arow + i * 64;
            const size_t go = (size_t)(m0 + r) * MPAD + k0 + acol;
            *(uint4*)&Ah[r][acol] = *(const uint4*)&g_msgh[go];
            *(uint4*)&Al[r][acol] = *(const uint4*)&g_msgl[go];
        }
        // ---- B tiles: 64 x 32 bf16, hi & lo (1 uint4 per thread each) -------
        {
            const size_t go = (size_t)(n0 + arow) * MPAD + k0 + acol;
            *(uint4*)&Bh[arow][acol] = *(const uint4*)&g_Wth[go];
            *(uint4*)&Bl[arow][acol] = *(const uint4*)&g_Wtl[go];
        }
        __syncthreads();

        #pragma unroll
        for (int kk = 0; kk < 32; kk += 16) {
            uint32_t ah[2][4], al[2][4], bh[4][2], bl[4][2];
            #pragma unroll
            for (int mt = 0; mt < 2; mt++) {
                const int row = wm + mt * 16;
                ah[mt][0] = *(const uint32_t*)&Ah[row + g    ][kk + 2*tg    ];
                ah[mt][1] = *(const uint32_t*)&Ah[row + g + 8][kk + 2*tg    ];
                ah[mt][2] = *(const uint32_t*)&Ah[row + g    ][kk + 2*tg + 8];
                ah[mt][3] = *(const uint32_t*)&Ah[row + g + 8][kk + 2*tg + 8];
                al[mt][0] = *(const uint32_t*)&Al[row + g    ][kk + 2*tg    ];
                al[mt][1] = *(const uint32_t*)&Al[row + g + 8][kk + 2*tg    ];
                al[mt][2] = *(const uint32_t*)&Al[row + g    ][kk + 2*tg + 8];
                al[mt][3] = *(const uint32_t*)&Al[row + g + 8][kk + 2*tg + 8];
            }
            #pragma unroll
            for (int nt = 0; nt < 4; nt++) {
                const int col = wn + nt * 8 + g;
                bh[nt][0] = *(const uint32_t*)&Bh[col][kk + 2*tg    ];
                bh[nt][1] = *(const uint32_t*)&Bh[col][kk + 2*tg + 8];
                bl[nt][0] = *(const uint32_t*)&Bl[col][kk + 2*tg    ];
                bl[nt][1] = *(const uint32_t*)&Bl[col][kk + 2*tg + 8];
            }
            #pragma unroll
            for (int mt = 0; mt < 2; mt++)
                #pragma unroll
                for (int nt = 0; nt < 4; nt++) {
                    mma_bf16(d[mt][nt], ah[mt], bh[nt]);  // hi*hi
                    mma_bf16(d[mt][nt], ah[mt], bl[nt]);  // hi*lo
                    mma_bf16(d[mt][nt], al[mt], bh[nt]);  // lo*hi
                }
        }
        __syncthreads();
    }

    // ---- epilogue: write g_G (fp32, stride 300), bounds gn < 300 ----
    #pragma unroll
    for (int mt = 0; mt < 2; mt++) {
        const int gm = m0 + wm + mt * 16 + g;
        #pragma unroll
        for (int nt = 0; nt < 4; nt++) {
            const int gn = n0 + wn + nt * 8 + 2 * tg;
            if (gn < HIDDEN) {
                *(float2*)&g_G[(size_t)gm * HIDDEN + gn]       = make_float2(d[mt][nt][0], d[mt][nt][1]);
                *(float2*)&g_G[(size_t)(gm + 8) * HIDDEN + gn] = make_float2(d[mt][nt][2], d[mt][nt][3]);
            }
        }
    }
}

// ---------------- split + transpose W_h into padded bf16 hi/lo ---------------
__global__ void split_Wh_k(const float* __restrict__ W_h)
{
    const int i = blockIdx.x * blockDim.x + threadIdx.x;
    if (i >= MPAD * MPAD) return;
    const int n = i / MPAD;
    const int k = i - n * MPAD;
    __nv_bfloat16 h = __float2bfloat16(0.f), l = h;
    if (n < HIDDEN && k < HIDDEN) bsplit(W_h[k * HIDDEN + n], h, l);
    g_Wth[i] = h;
    g_Wtl[i] = l;
}

// ---------------- zero msg pad columns ---------------------------------------
__global__ void pad_msg_k()
{
    const int i = blockIdx.x * blockDim.x + threadIdx.x;
    if (i >= N_EDGES * (MPAD - HIDDEN)) return;
    const int e = i / (MPAD - HIDDEN);
    const int j = i - e * (MPAD - HIDDEN);
    const __nv_bfloat16 z = __float2bfloat16(0.f);
    g_msgh[(size_t)e * MPAD + HIDDEN + j] = z;
    g_msgl[(size_t)e * MPAD + HIDDEN + j] = z;
}

// ---------------- SIMT SGEMM for modes 1 (W_i) and 2 (W_o) -------------------
template<int MODE>
__launch_bounds__(256)
__global__ void sgemm_k(const float* __restrict__ A1,
                        const float* __restrict__ B,
                        const float* __restrict__ bias,
                        const int*  __restrict__ molids,
                        float* __restrict__ out)
{
    const int K1 = (MODE == 1) ? EDGE_FDIM : NODE_FDIM;
    const int K  = (MODE == 2) ? (NODE_FDIM + HIDDEN) : K1;
    const int N  = HIDDEN;

    __shared__ float As[16][132];
    __shared__ float Bs[16][64];

    const int t  = threadIdx.x;
    const int tx = t & 15;
    const int ty = t >> 4;
    const int m0 = blockIdx.y * 128;
    const int n0 = blockIdx.x * 64;

    float acc[8][4] = {};

    for (int k0 = 0; k0 < K; k0 += 16) {
        #pragma unroll
        for (int i = 0; i < 8; i++) {
            const int k  = t & 15;
            const int m  = (t >> 4) + i * 16;
            const int gk = k0 + k;
            float v = 0.f;
            if (gk < K) {
                const int gm = m0 + m;
                if (MODE == 1) {
                    v = A1[gm * EDGE_FDIM + gk];
                } else {
                    v = (gk < NODE_FDIM) ? A1[gm * NODE_FDIM + gk]
                                         : g_S[gm * HIDDEN + (gk - NODE_FDIM)];
                }
            }
            As[k][m] = v;
        }
        #pragma unroll
        for (int i = 0; i < 4; i++) {
            const int k  = (t >> 6) + i * 4;
            const int n  = t & 63;
            const int gk = k0 + k;
            const int gn = n0 + n;
            Bs[k][n] = (gk < K && gn < N) ? B[gk * N + gn] : 0.f;
        }
        __syncthreads();

        #pragma unroll
        for (int kk = 0; kk < 16; kk++) {
            const float4 a0 = *(const float4*)&As[kk][ty * 8];
            const float4 a1 = *(const float4*)&As[kk][ty * 8 + 4];
            const float4 b  = *(const float4*)&Bs[kk][tx * 4];
            const float av[8] = {a0.x,a0.y,a0.z,a0.w,a1.x,a1.y,a1.z,a1.w};
            const float bv[4] = {b.x,b.y,b.z,b.w};
            #pragma unroll
            for (int i = 0; i < 8; i++)
                #pragma unroll
                for (int j = 0; j < 4; j++)
                    acc[i][j] = fmaf(av[i], bv[j], acc[i][j]);
        }
        __syncthreads();
    }

    #pragma unroll
    for (int i = 0; i < 8; i++) {
        const int gm = m0 + ty * 8 + i;
        int molid = 0;
        if (MODE == 2) molid = molids[gm];
        #pragma unroll
        for (int j = 0; j < 4; j++) {
            const int gn = n0 + tx * 4 + j;
            if (gn < N) {
                const float v = acc[i][j];
                if (MODE == 1) {
                    g_inp[gm * HIDDEN + gn] = v;
                    __nv_bfloat16 h, l;
                    bsplit(fmaxf(v, 0.f), h, l);
                    g_msgh[(size_t)gm * MPAD + gn] = h;
                    g_msgl[(size_t)gm * MPAD + gn] = l;
                } else {
                    const float h = fmaxf(v + bias[gn], 0.f);
                    atomicAdd(&out[molid * HIDDEN + gn], h);
                }
            }
        }
    }
}

// ---------------- S[v] = sum_{k<6} X[n2e[v,k]] --------------------------------
// SRC 0: read g_G (fp32 stride 300) ; SRC 1: read g_msgh+g_msgl (bf16 stride 320)
template<int SRC>
__global__ void node_agg_k(const int* __restrict__ n2e)
{
    const int idx = blockIdx.x * blockDim.x + threadIdx.x;
    if (idx >= N_NODES * H4) return;
    const int v = idx / H4;
    const int c = idx - v * H4;
    float4 s = make_float4(0.f, 0.f, 0.f, 0.f);
    #pragma unroll
    for (int k = 0; k < MAX_NB; k++) {
        const int e = __ldg(&n2e[v * MAX_NB + k]);
        if (SRC == 0) {
            const float4 gg = __ldg(&((const float4*)g_G)[e * H4 + c]);
            s.x += gg.x; s.y += gg.y; s.z += gg.z; s.w += gg.w;
        } else {
            const size_t off = (size_t)e * MPAD + c * 4;
            const uint2 uh = *(const uint2*)&g_msgh[off];
            const uint2 ul = *(const uint2*)&g_msgl[off];
            const float2 h0 = __bfloat1622float2(*(const __nv_bfloat162*)&uh.x);
            const float2 h1 = __bfloat1622float2(*(const __nv_bfloat162*)&uh.y);
            const float2 l0 = __bfloat1622float2(*(const __nv_bfloat162*)&ul.x);
            const float2 l1 = __bfloat1622float2(*(const __nv_bfloat162*)&ul.y);
            s.x += h0.x + l0.x; s.y += h0.y + l0.y;
            s.z += h1.x + l1.x; s.w += h1.y + l1.y;
        }
    }
    ((float4*)g_S)[idx] = s;
}

// -------- msg[e] = relu(inp[e] + S[e2n[e]] - G[rev[e]])  (write bf16 hi/lo) ---
__global__ void edge_update_k(const int* __restrict__ e2n,
                              const int* __restrict__ e2rev)
{
    const int idx = blockIdx.x * blockDim.x + threadIdx.x;
    if (idx >= N_EDGES * H4) return;
    const int e = idx / H4;
    const int c = idx - e * H4;
    const int v   = __ldg(&e2n[e]);
    const int rev = __ldg(&e2rev[e]);
    const float4 pi = ((const float4*)g_inp)[idx];
    const float4 ps = __ldg(&((const float4*)g_S)[v * H4 + c]);
    const float4 pg = __ldg(&((const float4*)g_G)[rev * H4 + c]);
    float m[4];
    m[0] = fmaxf(pi.x + ps.x - pg.x, 0.f);
    m[1] = fmaxf(pi.y + ps.y - pg.y, 0.f);
    m[2] = fmaxf(pi.z + ps.z - pg.z, 0.f);
    m[3] = fmaxf(pi.w + ps.w - pg.w, 0.f);
    __nv_bfloat16 h[4], l[4];
    #pragma unroll
    for (int j = 0; j < 4; j++) bsplit(m[j], h[j], l[j]);
    const size_t off = (size_t)e * MPAD + c * 4;
    *(uint2*)&g_msgh[off] = *(const uint2*)h;
    *(uint2*)&g_msgl[off] = *(const uint2*)l;
}

// ---------------- init / count / divide ---------------------------------------
__global__ void zero_out_k(float* __restrict__ out)
{
    const int i = blockIdx.x * blockDim.x + threadIdx.x;
    if (i < N_MOLS * HIDDEN) out[i] = 0.f;
    if (i < N_MOLS) g_cnt[i] = 0;
}

__global__ void count_k(const int* __restrict__ mol_ids)
{
    const int v = blockIdx.x * blockDim.x + threadIdx.x;
    if (v < N_NODES) atomicAdd(&g_cnt[mol_ids[v]], 1);
}

__global__ void divide_k(float* __restrict__ out)
{
    const int i = blockIdx.x * blockDim.x + threadIdx.x;
    if (i >= N_MOLS * HIDDEN) return;
    const int m = i / HIDDEN;
    const int c = g_cnt[m];
    out[i] = (c > 0) ? out[i] / (float)c : 0.f;
}

// ------------------------------------------------------------------------------
extern "C" void kernel_launch(void* const* d_in, const int* in_sizes, int n_in,
                              void* d_out, int out_size)
{
    const float* f_nodes = (const float*)d_in[0];
    const float* f_edges = (const float*)d_in[1];
    const float* W_i     = (const float*)d_in[2];
    const float* W_h     = (const float*)d_in[3];
    const float* W_o     = (const float*)d_in[4];
    const float* b_o     = (const float*)d_in[5];
    const int*   n2e     = (const int*)d_in[6];
    const int*   e2n     = (const int*)d_in[7];
    const int*   e2rev   = (const int*)d_in[8];
    const int*   mol_ids = (const int*)d_in[9];
    float* out = (float*)d_out;

    zero_out_k<<<(N_MOLS * HIDDEN + 255) / 256, 256>>>(out);
    count_k<<<(N_NODES + 255) / 256, 256>>>(mol_ids);
    split_Wh_k<<<(MPAD * MPAD + 255) / 256, 256>>>(W_h);
    pad_msg_k<<<(N_EDGES * (MPAD - HIDDEN) + 255) / 256, 256>>>();

    const dim3 gridE((HIDDEN + 63) / 64, N_EDGES / 128);
    const dim3 gridN((HIDDEN + 63) / 64, N_NODES / 128);
    const dim3 gridT(MPAD / BN, N_EDGES / BM);   // (5, 800)

    // inp = f_edges @ W_i ; msg = relu(inp) (split bf16 hi/lo)
    sgemm_k<1><<<gridE, 256>>>(f_edges, W_i, nullptr, nullptr, nullptr);

    const int aggBlocks  = (N_NODES * H4 + 255) / 256;
    const int edgeBlocks = (N_EDGES * H4 + 255) / 256;

    for (int it = 0; it < DEPTH - 1; it++) {
        // G = msg @ W_h  (bf16 tensor cores, 3-term split)
        mma_gemm_Wh_k<<<gridT, 256>>>();
        // S[v] = sum_k G[n2e[v,k]]
        node_agg_k<0><<<aggBlocks, 256>>>(n2e);
        // msg[e] = relu(inp[e] + S[e2n[e]] - G[rev[e]]) -> bf16 hi/lo
        edge_update_k<<<edgeBlocks, 256>>>(e2n, e2rev);
    }

    // final neighbor sum of messages into S
    node_agg_k<1><<<aggBlocks, 256>>>(n2e);

    // node_hiddens = relu([f_nodes, S] @ W_o + b_o); atomic segment-sum to out
    sgemm_k<2><<<gridN, 256>>>(f_nodes, W_o, b_o, mol_ids, out);

    // mean
    divide_k<<<(N_MOLS * HIDDEN + 255) / 256, 256>>>(out);
}

// round 10
// speedup vs baseline: 1.6074x; 1.1868x over previous
#include <cuda_runtime.h>
#include <cuda_bf16.h>
#include <cstdint>

#define N_MOLS   2048
#define N_NODES  51200
#define N_EDGES  102400
#define MAX_NB   6
#define HIDDEN   300
#define NODE_FDIM 133
#define EDGE_FDIM 147
#define DEPTH    6
#define H4       75      // float4 per 300-col row
#define MPAD     320     // padded K stride for msg arrays (bf16 elems)
#define FEPAD    160     // padded K stride for f_edges bf16
#define CATPAD   448     // padded K stride for [f_nodes|S] bf16

// ---------------- scratch (static device globals; allocation-free) ----------
__device__ float g_inp [N_EDGES * HIDDEN];
__device__ __align__(16) __nv_bfloat16 g_msgh[N_EDGES * MPAD];
__device__ __align__(16) __nv_bfloat16 g_msgl[N_EDGES * MPAD];
__device__ float g_G   [N_EDGES * HIDDEN];
__device__ float g_S   [N_NODES * HIDDEN];
__device__ __align__(16) __nv_bfloat16 g_feh [N_EDGES * FEPAD];   // f_edges hi
__device__ __align__(16) __nv_bfloat16 g_fel [N_EDGES * FEPAD];   // f_edges lo
__device__ __align__(16) __nv_bfloat16 g_cath[N_NODES * CATPAD];  // [f_nodes|S] hi
__device__ __align__(16) __nv_bfloat16 g_catl[N_NODES * CATPAD];  // [f_nodes|S] lo
__device__ __align__(16) __nv_bfloat16 g_Wth [MPAD * MPAD];       // W_h^T  [320][320]
__device__ __align__(16) __nv_bfloat16 g_Wtl [MPAD * MPAD];
__device__ __align__(16) __nv_bfloat16 g_Wih [MPAD * FEPAD];      // W_i^T  [320][160]
__device__ __align__(16) __nv_bfloat16 g_Wil [MPAD * FEPAD];
__device__ __align__(16) __nv_bfloat16 g_Woh [MPAD * CATPAD];     // W_o^T  [320][448]
__device__ __align__(16) __nv_bfloat16 g_Wol [MPAD * CATPAD];
__device__ int   g_cnt [N_MOLS];

// ---------------- helpers ----------------------------------------------------
__device__ __forceinline__ void bsplit(float x, __nv_bfloat16& h, __nv_bfloat16& l) {
    h = __float2bfloat16(x);
    l = __float2bfloat16(x - __bfloat162float(h));
}

__device__ __forceinline__ void mma_bf16(float* d, const uint32_t* a, const uint32_t* b) {
    asm volatile(
        "mma.sync.aligned.m16n8k16.row.col.f32.bf16.bf16.f32 "
        "{%0,%1,%2,%3}, {%4,%5,%6,%7}, {%8,%9}, {%0,%1,%2,%3};\n"
        : "+f"(d[0]), "+f"(d[1]), "+f"(d[2]), "+f"(d[3])
        : "r"(a[0]), "r"(a[1]), "r"(a[2]), "r"(a[3]), "r"(b[0]), "r"(b[1]));
}

// ---------------- unified bf16 3-split tensor-core GEMM ----------------------
// MODE 0: g_G   = msg @ W_h          (A = g_msgh/l,  KSTR=320, KCH=10)
// MODE 1: inp/msg = f_edges @ W_i    (A = g_feh/l,   KSTR=160, KCH=5)
// MODE 2: out += relu([fn|S]@W_o+b)  (A = g_cath/l,  KSTR=448, KCH=14)
#define BM 128
#define BN 64
#define ASTR 40
template<int MODE, int KCH, int KSTR>
__launch_bounds__(256)
__global__ void mma_gemm_k(const float* __restrict__ bias,
                           const int*   __restrict__ molids,
                           float*       __restrict__ out)
{
    __shared__ __nv_bfloat16 Ah[BM][ASTR], Al[BM][ASTR];
    __shared__ __nv_bfloat16 Bh[BN][ASTR], Bl[BN][ASTR];

    const __nv_bfloat16* __restrict__ Asrc_h =
        (MODE == 0) ? g_msgh : (MODE == 1) ? g_feh : g_cath;
    const __nv_bfloat16* __restrict__ Asrc_l =
        (MODE == 0) ? g_msgl : (MODE == 1) ? g_fel : g_catl;
    const __nv_bfloat16* __restrict__ Bsrc_h =
        (MODE == 0) ? g_Wth : (MODE == 1) ? g_Wih : g_Woh;
    const __nv_bfloat16* __restrict__ Bsrc_l =
        (MODE == 0) ? g_Wtl : (MODE == 1) ? g_Wil : g_Wol;

    const int tid  = threadIdx.x;
    const int lane = tid & 31;
    const int wid  = tid >> 5;
    const int wm   = (wid >> 1) * 32;
    const int wn   = (wid & 1) * 32;
    const int g    = lane >> 2;
    const int tg   = lane & 3;
    const int m0   = blockIdx.y * BM;
    const int n0   = blockIdx.x * BN;

    const int arow = tid >> 2;
    const int acol = (tid & 3) * 8;

    float d[2][4][4];
    #pragma unroll
    for (int mt = 0; mt < 2; mt++)
        #pragma unroll
        for (int nt = 0; nt < 4; nt++)
            #pragma unroll
            for (int r = 0; r < 4; r++) d[mt][nt][r] = 0.f;

    for (int c = 0; c < KCH; c++) {
        const int k0 = c * 32;
        #pragma unroll
        for (int i = 0; i < 2; i++) {
            const int r = arow + i * 64;
            const size_t go = (size_t)(m0 + r) * KSTR + k0 + acol;
            *(uint4*)&Ah[r][acol] = *(const uint4*)&Asrc_h[go];
            *(uint4*)&Al[r][acol] = *(const uint4*)&Asrc_l[go];
        }
        {
            const size_t go = (size_t)(n0 + arow) * KSTR + k0 + acol;
            *(uint4*)&Bh[arow][acol] = *(const uint4*)&Bsrc_h[go];
            *(uint4*)&Bl[arow][acol] = *(const uint4*)&Bsrc_l[go];
        }
        __syncthreads();

        #pragma unroll
        for (int kk = 0; kk < 32; kk += 16) {
            uint32_t ah[2][4], al[2][4], bh[4][2], bl[4][2];
            #pragma unroll
            for (int mt = 0; mt < 2; mt++) {
                const int row = wm + mt * 16;
                ah[mt][0] = *(const uint32_t*)&Ah[row + g    ][kk + 2*tg    ];
                ah[mt][1] = *(const uint32_t*)&Ah[row + g + 8][kk + 2*tg    ];
                ah[mt][2] = *(const uint32_t*)&Ah[row + g    ][kk + 2*tg + 8];
                ah[mt][3] = *(const uint32_t*)&Ah[row + g + 8][kk + 2*tg + 8];
                al[mt][0] = *(const uint32_t*)&Al[row + g    ][kk + 2*tg    ];
                al[mt][1] = *(const uint32_t*)&Al[row + g + 8][kk + 2*tg    ];
                al[mt][2] = *(const uint32_t*)&Al[row + g    ][kk + 2*tg + 8];
                al[mt][3] = *(const uint32_t*)&Al[row + g + 8][kk + 2*tg + 8];
            }
            #pragma unroll
            for (int nt = 0; nt < 4; nt++) {
                const int col = wn + nt * 8 + g;
                bh[nt][0] = *(const uint32_t*)&Bh[col][kk + 2*tg    ];
                bh[nt][1] = *(const uint32_t*)&Bh[col][kk + 2*tg + 8];
                bl[nt][0] = *(const uint32_t*)&Bl[col][kk + 2*tg    ];
                bl[nt][1] = *(const uint32_t*)&Bl[col][kk + 2*tg + 8];
            }
            #pragma unroll
            for (int mt = 0; mt < 2; mt++)
                #pragma unroll
                for (int nt = 0; nt < 4; nt++) {
                    mma_bf16(d[mt][nt], ah[mt], bh[nt]);
                    mma_bf16(d[mt][nt], ah[mt], bl[nt]);
                    mma_bf16(d[mt][nt], al[mt], bh[nt]);
                }
        }
        __syncthreads();
    }

    // ---- epilogue ----
    #pragma unroll
    for (int mt = 0; mt < 2; mt++) {
        const int gm = m0 + wm + mt * 16 + g;
        int mol0 = 0, mol1 = 0;
        if (MODE == 2) { mol0 = molids[gm]; mol1 = molids[gm + 8]; }
        #pragma unroll
        for (int nt = 0; nt < 4; nt++) {
            const int gn = n0 + wn + nt * 8 + 2 * tg;
            if (gn < HIDDEN) {
                if (MODE == 0) {
                    *(float2*)&g_G[(size_t)gm * HIDDEN + gn]       = make_float2(d[mt][nt][0], d[mt][nt][1]);
                    *(float2*)&g_G[(size_t)(gm + 8) * HIDDEN + gn] = make_float2(d[mt][nt][2], d[mt][nt][3]);
                } else if (MODE == 1) {
                    *(float2*)&g_inp[(size_t)gm * HIDDEN + gn]       = make_float2(d[mt][nt][0], d[mt][nt][1]);
                    *(float2*)&g_inp[(size_t)(gm + 8) * HIDDEN + gn] = make_float2(d[mt][nt][2], d[mt][nt][3]);
                    __nv_bfloat16 h0, l0, h1, l1;
                    bsplit(fmaxf(d[mt][nt][0], 0.f), h0, l0);
                    bsplit(fmaxf(d[mt][nt][1], 0.f), h1, l1);
                    g_msgh[(size_t)gm * MPAD + gn]     = h0;
                    g_msgh[(size_t)gm * MPAD + gn + 1] = h1;
                    g_msgl[(size_t)gm * MPAD + gn]     = l0;
                    g_msgl[(size_t)gm * MPAD + gn + 1] = l1;
                    bsplit(fmaxf(d[mt][nt][2], 0.f), h0, l0);
                    bsplit(fmaxf(d[mt][nt][3], 0.f), h1, l1);
                    g_msgh[(size_t)(gm + 8) * MPAD + gn]     = h0;
                    g_msgh[(size_t)(gm + 8) * MPAD + gn + 1] = h1;
                    g_msgl[(size_t)(gm + 8) * MPAD + gn]     = l0;
                    g_msgl[(size_t)(gm + 8) * MPAD + gn + 1] = l1;
                } else {
                    const float b0 = bias[gn], b1 = bias[gn + 1];
                    atomicAdd(&out[mol0 * HIDDEN + gn],     fmaxf(d[mt][nt][0] + b0, 0.f));
                    atomicAdd(&out[mol0 * HIDDEN + gn + 1], fmaxf(d[mt][nt][1] + b1, 0.f));
                    atomicAdd(&out[mol1 * HIDDEN + gn],     fmaxf(d[mt][nt][2] + b0, 0.f));
                    atomicAdd(&out[mol1 * HIDDEN + gn + 1], fmaxf(d[mt][nt][3] + b1, 0.f));
                }
            }
        }
    }
}

// ---------------- weight split+transpose: W[K×300] -> Wt hi/lo [320×KP] ------
template<int K, int KP>
__global__ void split_W_k(const float* __restrict__ W)
{
    const int i = blockIdx.x * blockDim.x + threadIdx.x;
    if (i >= MPAD * KP) return;
    const int n = i / KP;
    const int k = i - n * KP;
    __nv_bfloat16 h = __float2bfloat16(0.f), l = h;
    if (n < HIDDEN && k < K) bsplit(W[k * HIDDEN + n], h, l);
    ((__nv_bfloat16*)((KP == MPAD) ? g_Wth : (KP == FEPAD) ? g_Wih : g_Woh))[i] = h;
    ((__nv_bfloat16*)((KP == MPAD) ? g_Wtl : (KP == FEPAD) ? g_Wil : g_Wol))[i] = l;
}

// ---------------- split f_edges fp32 -> bf16 hi/lo padded --------------------
__global__ void split_fe_k(const float* __restrict__ fe)
{
    const int i = blockIdx.x * blockDim.x + threadIdx.x;
    if (i >= N_EDGES * FEPAD) return;
    const int m = i / FEPAD;
    const int k = i - m * FEPAD;
    __nv_bfloat16 h = __float2bfloat16(0.f), l = h;
    if (k < EDGE_FDIM) bsplit(fe[m * EDGE_FDIM + k], h, l);
    g_feh[i] = h;
    g_fel[i] = l;
}

// ---------------- split concat [f_nodes | g_S] -> bf16 hi/lo padded ----------
__global__ void split_cat_k(const float* __restrict__ fn)
{
    const int i = blockIdx.x * blockDim.x + threadIdx.x;
    if (i >= N_NODES * CATPAD) return;
    const int m = i / CATPAD;
    const int k = i - m * CATPAD;
    __nv_bfloat16 h = __float2bfloat16(0.f), l = h;
    if (k < NODE_FDIM) bsplit(fn[m * NODE_FDIM + k], h, l);
    else if (k < NODE_FDIM + HIDDEN) bsplit(g_S[m * HIDDEN + (k - NODE_FDIM)], h, l);
    g_cath[i] = h;
    g_catl[i] = l;
}

// ---------------- zero msg pad columns ---------------------------------------
__global__ void pad_msg_k()
{
    const int i = blockIdx.x * blockDim.x + threadIdx.x;
    if (i >= N_EDGES * (MPAD - HIDDEN)) return;
    const int e = i / (MPAD - HIDDEN);
    const int j = i - e * (MPAD - HIDDEN);
    const __nv_bfloat16 z = __float2bfloat16(0.f);
    g_msgh[(size_t)e * MPAD + HIDDEN + j] = z;
    g_msgl[(size_t)e * MPAD + HIDDEN + j] = z;
}

// ---------------- S[v] = sum_{k<6} X[n2e[v,k]] --------------------------------
template<int SRC>
__global__ void node_agg_k(const int* __restrict__ n2e)
{
    const int idx = blockIdx.x * blockDim.x + threadIdx.x;
    if (idx >= N_NODES * H4) return;
    const int v = idx / H4;
    const int c = idx - v * H4;
    float4 s = make_float4(0.f, 0.f, 0.f, 0.f);
    #pragma unroll
    for (int k = 0; k < MAX_NB; k++) {
        const int e = __ldg(&n2e[v * MAX_NB + k]);
        if (SRC == 0) {
            const float4 gg = __ldg(&((const float4*)g_G)[e * H4 + c]);
            s.x += gg.x; s.y += gg.y; s.z += gg.z; s.w += gg.w;
        } else {
            const size_t off = (size_t)e * MPAD + c * 4;
            const uint2 uh = *(const uint2*)&g_msgh[off];
            const uint2 ul = *(const uint2*)&g_msgl[off];
            const float2 h0 = __bfloat1622float2(*(const __nv_bfloat162*)&uh.x);
            const float2 h1 = __bfloat1622float2(*(const __nv_bfloat162*)&uh.y);
            const float2 l0 = __bfloat1622float2(*(const __nv_bfloat162*)&ul.x);
            const float2 l1 = __bfloat1622float2(*(const __nv_bfloat162*)&ul.y);
            s.x += h0.x + l0.x; s.y += h0.y + l0.y;
            s.z += h1.x + l1.x; s.w += h1.y + l1.y;
        }
    }
    ((float4*)g_S)[idx] = s;
}

// -------- msg[e] = relu(inp[e] + S[e2n[e]] - G[rev[e]])  (write bf16 hi/lo) ---
__global__ void edge_update_k(const int* __restrict__ e2n,
                              const int* __restrict__ e2rev)
{
    const int idx = blockIdx.x * blockDim.x + threadIdx.x;
    if (idx >= N_EDGES * H4) return;
    const int e = idx / H4;
    const int c = idx - e * H4;
    const int v   = __ldg(&e2n[e]);
    const int rev = __ldg(&e2rev[e]);
    const float4 pi = ((const float4*)g_inp)[idx];
    const float4 ps = __ldg(&((const float4*)g_S)[v * H4 + c]);
    const float4 pg = __ldg(&((const float4*)g_G)[rev * H4 + c]);
    float m[4];
    m[0] = fmaxf(pi.x + ps.x - pg.x, 0.f);
    m[1] = fmaxf(pi.y + ps.y - pg.y, 0.f);
    m[2] = fmaxf(pi.z + ps.z - pg.z, 0.f);
    m[3] = fmaxf(pi.w + ps.w - pg.w, 0.f);
    __nv_bfloat16 h[4], l[4];
    #pragma unroll
    for (int j = 0; j < 4; j++) bsplit(m[j], h[j], l[j]);
    const size_t off = (size_t)e * MPAD + c * 4;
    *(uint2*)&g_msgh[off] = *(const uint2*)h;
    *(uint2*)&g_msgl[off] = *(const uint2*)l;
}

// ---------------- init / count / divide ---------------------------------------
__global__ void zero_out_k(float* __restrict__ out)
{
    const int i = blockIdx.x * blockDim.x + threadIdx.x;
    if (i < N_MOLS * HIDDEN) out[i] = 0.f;
    if (i < N_MOLS) g_cnt[i] = 0;
}

__global__ void count_k(const int* __restrict__ mol_ids)
{
    const int v = blockIdx.x * blockDim.x + threadIdx.x;
    if (v < N_NODES) atomicAdd(&g_cnt[mol_ids[v]], 1);
}

__global__ void divide_k(float* __restrict__ out)
{
    const int i = blockIdx.x * blockDim.x + threadIdx.x;
    if (i >= N_MOLS * HIDDEN) return;
    const int m = i / HIDDEN;
    const int c = g_cnt[m];
    out[i] = (c > 0) ? out[i] / (float)c : 0.f;
}

// ------------------------------------------------------------------------------
extern "C" void kernel_launch(void* const* d_in, const int* in_sizes, int n_in,
                              void* d_out, int out_size)
{
    const float* f_nodes = (const float*)d_in[0];
    const float* f_edges = (const float*)d_in[1];
    const float* W_i     = (const float*)d_in[2];
    const float* W_h     = (const float*)d_in[3];
    const float* W_o     = (const float*)d_in[4];
    const float* b_o     = (const float*)d_in[5];
    const int*   n2e     = (const int*)d_in[6];
    const int*   e2n     = (const int*)d_in[7];
    const int*   e2rev   = (const int*)d_in[8];
    const int*   mol_ids = (const int*)d_in[9];
    float* out = (float*)d_out;

    zero_out_k<<<(N_MOLS * HIDDEN + 255) / 256, 256>>>(out);
    count_k<<<(N_NODES + 255) / 256, 256>>>(mol_ids);
    split_W_k<HIDDEN, MPAD>  <<<(MPAD * MPAD   + 255) / 256, 256>>>(W_h);
    split_W_k<EDGE_FDIM, FEPAD><<<(MPAD * FEPAD + 255) / 256, 256>>>(W_i);
    split_W_k<NODE_FDIM + HIDDEN, CATPAD><<<(MPAD * CATPAD + 255) / 256, 256>>>(W_o);
    split_fe_k<<<(N_EDGES * FEPAD + 255) / 256, 256>>>(f_edges);
    pad_msg_k<<<(N_EDGES * (MPAD - HIDDEN) + 255) / 256, 256>>>();

    const dim3 gridE(MPAD / BN, N_EDGES / BM);   // (5, 800)
    const dim3 gridN(MPAD / BN, N_NODES / BM);   // (5, 400)

    // inp = f_edges @ W_i ; msg = relu(inp) split bf16 (tensor cores)
    mma_gemm_k<1, 5, FEPAD><<<gridE, 256>>>(nullptr, nullptr, nullptr);

    const int aggBlocks  = (N_NODES * H4 + 255) / 256;
    const int edgeBlocks = (N_EDGES * H4 + 255) / 256;

    for (int it = 0; it < DEPTH - 1; it++) {
        // G = msg @ W_h (tensor cores)
        mma_gemm_k<0, 10, MPAD><<<gridE, 256>>>(nullptr, nullptr, nullptr);
        // S[v] = sum_k G[n2e[v,k]]
        node_agg_k<0><<<aggBlocks, 256>>>(n2e);
        // msg[e] = relu(inp[e] + S[e2n[e]] - G[rev[e]]) -> bf16 hi/lo
        edge_update_k<<<edgeBlocks, 256>>>(e2n, e2rev);
    }

    // final neighbor sum of messages into S
    node_agg_k<1><<<aggBlocks, 256>>>(n2e);

    // concat split, then out GEMM (tensor cores, atomic seg-sum epilogue)
    split_cat_k<<<(N_NODES * CATPAD + 255) / 256, 256>>>(f_nodes);
    mma_gemm_k<2, 14, CATPAD><<<gridN, 256>>>(b_o, mol_ids, out);

    // mean
    divide_k<<<(N_MOLS * HIDDEN + 255) / 256, 256>>>(out);
}

// round 12
// speedup vs baseline: 1.8436x; 1.1469x over previous
#include <cuda_runtime.h>
#include <cuda_bf16.h>
#include <cstdint>

#define N_MOLS   2048
#define N_NODES  51200
#define N_EDGES  102400
#define MAX_NB   6
#define HIDDEN   300
#define NODE_FDIM 133
#define EDGE_FDIM 147
#define DEPTH    6
#define H4       75      // float4 per 300-col row
#define MPAD     320     // padded K stride for msg arrays (bf16 elems)
#define FEPAD    160     // padded K stride for f_edges bf16
#define CATPAD   448     // padded K stride for [f_nodes|S] bf16

// ---------------- scratch (static device globals; allocation-free) ----------
__device__ float g_inp [N_EDGES * HIDDEN];
__device__ __align__(16) __nv_bfloat16 g_msgh[N_EDGES * MPAD];
__device__ __align__(16) __nv_bfloat16 g_msgl[N_EDGES * MPAD];
__device__ float g_G   [N_EDGES * HIDDEN];
__device__ float g_S   [N_NODES * HIDDEN];
__device__ __align__(16) __nv_bfloat16 g_feh [N_EDGES * FEPAD];
__device__ __align__(16) __nv_bfloat16 g_fel [N_EDGES * FEPAD];
__device__ __align__(16) __nv_bfloat16 g_cath[N_NODES * CATPAD];
__device__ __align__(16) __nv_bfloat16 g_catl[N_NODES * CATPAD];
__device__ __align__(16) __nv_bfloat16 g_Wth [MPAD * MPAD];
__device__ __align__(16) __nv_bfloat16 g_Wtl [MPAD * MPAD];
__device__ __align__(16) __nv_bfloat16 g_Wih [MPAD * FEPAD];
__device__ __align__(16) __nv_bfloat16 g_Wil [MPAD * FEPAD];
__device__ __align__(16) __nv_bfloat16 g_Woh [MPAD * CATPAD];
__device__ __align__(16) __nv_bfloat16 g_Wol [MPAD * CATPAD];
__device__ int   g_cnt [N_MOLS];

// ---------------- helpers ----------------------------------------------------
__device__ __forceinline__ void bsplit(float x, __nv_bfloat16& h, __nv_bfloat16& l) {
    h = __float2bfloat16(x);
    l = __float2bfloat16(x - __bfloat162float(h));
}

__device__ __forceinline__ void mma_bf16(float* d, const uint32_t* a, const uint32_t* b) {
    asm volatile(
        "mma.sync.aligned.m16n8k16.row.col.f32.bf16.bf16.f32 "
        "{%0,%1,%2,%3}, {%4,%5,%6,%7}, {%8,%9}, {%0,%1,%2,%3};\n"
        : "+f"(d[0]), "+f"(d[1]), "+f"(d[2]), "+f"(d[3])
        : "r"(a[0]), "r"(a[1]), "r"(a[2]), "r"(a[3]), "r"(b[0]), "r"(b[1]));
}

__device__ __forceinline__ void cp16(__nv_bfloat16* dst, const __nv_bfloat16* src) {
    const uint32_t sa = (uint32_t)__cvta_generic_to_shared(dst);
    asm volatile("cp.async.cg.shared.global [%0], [%1], 16;\n" :: "r"(sa), "l"(src));
}
__device__ __forceinline__ void cp_commit() {
    asm volatile("cp.async.commit_group;\n");
}
template<int N>
__device__ __forceinline__ void cp_wait() {
    asm volatile("cp.async.wait_group %0;\n" :: "n"(N));
}

// ---------------- unified bf16 3-split tensor-core GEMM (cp.async 2-stage) ---
// MODE 0: g_G   = msg @ W_h          (KSTR=320, KCH=10)
// MODE 1: inp/msg = f_edges @ W_i    (KSTR=160, KCH=5)
// MODE 2: out += relu([fn|S]@W_o+b)  (KSTR=448, KCH=14)
#define BM 128
#define BN 64
#define ASTR 40
#define A_SZ (BM * ASTR)    // 5120 elems
#define B_SZ (BN * ASTR)    // 2560 elems
#define SMEM_ELEMS (4 * A_SZ + 4 * B_SZ)         // 30720 elems
#define SMEM_BYTES (SMEM_ELEMS * 2)              // 61440 bytes

template<int MODE, int KCH, int KSTR>
__launch_bounds__(256)
__global__ void mma_gemm_k(const float* __restrict__ bias,
                           const int*   __restrict__ molids,
                           float*       __restrict__ out)
{
    extern __shared__ __nv_bfloat16 sm[];
    __nv_bfloat16* Ah = sm;                       // [2][BM][ASTR]
    __nv_bfloat16* Al = sm + 2 * A_SZ;            // [2][BM][ASTR]
    __nv_bfloat16* Bh = sm + 4 * A_SZ;            // [2][BN][ASTR]
    __nv_bfloat16* Bl = sm + 4 * A_SZ + 2 * B_SZ; // [2][BN][ASTR]

    const __nv_bfloat16* __restrict__ Asrc_h =
        (MODE == 0) ? g_msgh : (MODE == 1) ? g_feh : g_cath;
    const __nv_bfloat16* __restrict__ Asrc_l =
        (MODE == 0) ? g_msgl : (MODE == 1) ? g_fel : g_catl;
    const __nv_bfloat16* __restrict__ Bsrc_h =
        (MODE == 0) ? g_Wth : (MODE == 1) ? g_Wih : g_Woh;
    const __nv_bfloat16* __restrict__ Bsrc_l =
        (MODE == 0) ? g_Wtl : (MODE == 1) ? g_Wil : g_Wol;

    const int tid  = threadIdx.x;
    const int lane = tid & 31;
    const int wid  = tid >> 5;
    const int wm   = (wid >> 1) * 32;
    const int wn   = (wid & 1) * 32;
    const int g    = lane >> 2;
    const int tg   = lane & 3;
    const int m0   = blockIdx.y * BM;
    const int n0   = blockIdx.x * BN;

    const int arow = tid >> 2;
    const int acol = (tid & 3) * 8;

    float d[2][4][4];
    #pragma unroll
    for (int mt = 0; mt < 2; mt++)
        #pragma unroll
        for (int nt = 0; nt < 4; nt++)
            #pragma unroll
            for (int r = 0; r < 4; r++) d[mt][nt][r] = 0.f;

    // issue async loads for chunk c into stage st
    auto issue = [&](int c, int st) {
        const int k0 = c * 32;
        #pragma unroll
        for (int i = 0; i < 2; i++) {
            const int r = arow + i * 64;
            const size_t go = (size_t)(m0 + r) * KSTR + k0 + acol;
            cp16(Ah + st * A_SZ + r * ASTR + acol, Asrc_h + go);
            cp16(Al + st * A_SZ + r * ASTR + acol, Asrc_l + go);
        }
        const size_t go = (size_t)(n0 + arow) * KSTR + k0 + acol;
        cp16(Bh + st * B_SZ + arow * ASTR + acol, Bsrc_h + go);
        cp16(Bl + st * B_SZ + arow * ASTR + acol, Bsrc_l + go);
        cp_commit();
    };

    issue(0, 0);

    for (int c = 0; c < KCH; c++) {
        const int st = c & 1;
        if (c + 1 < KCH) {
            issue(c + 1, (c + 1) & 1);
            cp_wait<1>();
        } else {
            cp_wait<0>();
        }
        __syncthreads();

        const __nv_bfloat16* sAh = Ah + st * A_SZ;
        const __nv_bfloat16* sAl = Al + st * A_SZ;
        const __nv_bfloat16* sBh = Bh + st * B_SZ;
        const __nv_bfloat16* sBl = Bl + st * B_SZ;

        #pragma unroll
        for (int kk = 0; kk < 32; kk += 16) {
            uint32_t ah[2][4], al[2][4], bh[4][2], bl[4][2];
            #pragma unroll
            for (int mt = 0; mt < 2; mt++) {
                const int row = wm + mt * 16;
                ah[mt][0] = *(const uint32_t*)&sAh[(row + g    ) * ASTR + kk + 2*tg    ];
                ah[mt][1] = *(const uint32_t*)&sAh[(row + g + 8) * ASTR + kk + 2*tg    ];
                ah[mt][2] = *(const uint32_t*)&sAh[(row + g    ) * ASTR + kk + 2*tg + 8];
                ah[mt][3] = *(const uint32_t*)&sAh[(row + g + 8) * ASTR + kk + 2*tg + 8];
                al[mt][0] = *(const uint32_t*)&sAl[(row + g    ) * ASTR + kk + 2*tg    ];
                al[mt][1] = *(const uint32_t*)&sAl[(row + g + 8) * ASTR + kk + 2*tg    ];
                al[mt][2] = *(const uint32_t*)&sAl[(row + g    ) * ASTR + kk + 2*tg + 8];
                al[mt][3] = *(const uint32_t*)&sAl[(row + g + 8) * ASTR + kk + 2*tg + 8];
            }
            #pragma unroll
            for (int nt = 0; nt < 4; nt++) {
                const int col = wn + nt * 8 + g;
                bh[nt][0] = *(const uint32_t*)&sBh[col * ASTR + kk + 2*tg    ];
                bh[nt][1] = *(const uint32_t*)&sBh[col * ASTR + kk + 2*tg + 8];
                bl[nt][0] = *(const uint32_t*)&sBl[col * ASTR + kk + 2*tg    ];
                bl[nt][1] = *(const uint32_t*)&sBl[col * ASTR + kk + 2*tg + 8];
            }
            #pragma unroll
            for (int mt = 0; mt < 2; mt++)
                #pragma unroll
                for (int nt = 0; nt < 4; nt++) {
                    mma_bf16(d[mt][nt], ah[mt], bh[nt]);
                    mma_bf16(d[mt][nt], ah[mt], bl[nt]);
                    mma_bf16(d[mt][nt], al[mt], bh[nt]);
                }
        }
        __syncthreads();
    }

    // ---- epilogue ----
    #pragma unroll
    for (int mt = 0; mt < 2; mt++) {
        const int gm = m0 + wm + mt * 16 + g;
        int mol0 = 0, mol1 = 0;
        if (MODE == 2) { mol0 = molids[gm]; mol1 = molids[gm + 8]; }
        #pragma unroll
        for (int nt = 0; nt < 4; nt++) {
            const int gn = n0 + wn + nt * 8 + 2 * tg;
            if (gn < HIDDEN) {
                if (MODE == 0) {
                    *(float2*)&g_G[(size_t)gm * HIDDEN + gn]       = make_float2(d[mt][nt][0], d[mt][nt][1]);
                    *(float2*)&g_G[(size_t)(gm + 8) * HIDDEN + gn] = make_float2(d[mt][nt][2], d[mt][nt][3]);
                } else if (MODE == 1) {
                    *(float2*)&g_inp[(size_t)gm * HIDDEN + gn]       = make_float2(d[mt][nt][0], d[mt][nt][1]);
                    *(float2*)&g_inp[(size_t)(gm + 8) * HIDDEN + gn] = make_float2(d[mt][nt][2], d[mt][nt][3]);
                    __nv_bfloat16 h0, l0, h1, l1;
                    bsplit(fmaxf(d[mt][nt][0], 0.f), h0, l0);
                    bsplit(fmaxf(d[mt][nt][1], 0.f), h1, l1);
                    g_msgh[(size_t)gm * MPAD + gn]     = h0;
                    g_msgh[(size_t)gm * MPAD + gn + 1] = h1;
                    g_msgl[(size_t)gm * MPAD + gn]     = l0;
                    g_msgl[(size_t)gm * MPAD + gn + 1] = l1;
                    bsplit(fmaxf(d[mt][nt][2], 0.f), h0, l0);
                    bsplit(fmaxf(d[mt][nt][3], 0.f), h1, l1);
                    g_msgh[(size_t)(gm + 8) * MPAD + gn]     = h0;
                    g_msgh[(size_t)(gm + 8) * MPAD + gn + 1] = h1;
                    g_msgl[(size_t)(gm + 8) * MPAD + gn]     = l0;
                    g_msgl[(size_t)(gm + 8) * MPAD + gn + 1] = l1;
                } else {
                    const float b0 = bias[gn], b1 = bias[gn + 1];
                    atomicAdd(&out[mol0 * HIDDEN + gn],     fmaxf(d[mt][nt][0] + b0, 0.f));
                    atomicAdd(&out[mol0 * HIDDEN + gn + 1], fmaxf(d[mt][nt][1] + b1, 0.f));
                    atomicAdd(&out[mol1 * HIDDEN + gn],     fmaxf(d[mt][nt][2] + b0, 0.f));
                    atomicAdd(&out[mol1 * HIDDEN + gn + 1], fmaxf(d[mt][nt][3] + b1, 0.f));
                }
            }
        }
    }
}

// ---------------- weight split+transpose: W[K×300] -> Wt hi/lo [320×KP] ------
template<int K, int KP>
__global__ void split_W_k(const float* __restrict__ W)
{
    const int i = blockIdx.x * blockDim.x + threadIdx.x;
    if (i >= MPAD * KP) return;
    const int n = i / KP;
    const int k = i - n * KP;
    __nv_bfloat16 h = __float2bfloat16(0.f), l = h;
    if (n < HIDDEN && k < K) bsplit(W[k * HIDDEN + n], h, l);
    ((__nv_bfloat16*)((KP == MPAD) ? g_Wth : (KP == FEPAD) ? g_Wih : g_Woh))[i] = h;
    ((__nv_bfloat16*)((KP == MPAD) ? g_Wtl : (KP == FEPAD) ? g_Wil : g_Wol))[i] = l;
}

// ---------------- split f_edges fp32 -> bf16 hi/lo padded --------------------
__global__ void split_fe_k(const float* __restrict__ fe)
{
    const int i = blockIdx.x * blockDim.x + threadIdx.x;
    if (i >= N_EDGES * FEPAD) return;
    const int m = i / FEPAD;
    const int k = i - m * FEPAD;
    __nv_bfloat16 h = __float2bfloat16(0.f), l = h;
    if (k < EDGE_FDIM) bsplit(fe[m * EDGE_FDIM + k], h, l);
    g_feh[i] = h;
    g_fel[i] = l;
}

// ---------------- split concat [f_nodes | g_S] -> bf16 hi/lo padded ----------
__global__ void split_cat_k(const float* __restrict__ fn)
{
    const int i = blockIdx.x * blockDim.x + threadIdx.x;
    if (i >= N_NODES * CATPAD) return;
    const int m = i / CATPAD;
    const int k = i - m * CATPAD;
    __nv_bfloat16 h = __float2bfloat16(0.f), l = h;
    if (k < NODE_FDIM) bsplit(fn[m * NODE_FDIM + k], h, l);
    else if (k < NODE_FDIM + HIDDEN) bsplit(g_S[m * HIDDEN + (k - NODE_FDIM)], h, l);
    g_cath[i] = h;
    g_catl[i] = l;
}

// ---------------- zero msg pad columns ---------------------------------------
__global__ void pad_msg_k()
{
    const int i = blockIdx.x * blockDim.x + threadIdx.x;
    if (i >= N_EDGES * (MPAD - HIDDEN)) return;
    const int e = i / (MPAD - HIDDEN);
    const int j = i - e * (MPAD - HIDDEN);
    const __nv_bfloat16 z = __float2bfloat16(0.f);
    g_msgh[(size_t)e * MPAD + HIDDEN + j] = z;
    g_msgl[(size_t)e * MPAD + HIDDEN + j] = z;
}

// ---------------- S[v] = sum_{k<6} X[n2e[v,k]] --------------------------------
template<int SRC>
__global__ void node_agg_k(const int* __restrict__ n2e)
{
    const int idx = blockIdx.x * blockDim.x + threadIdx.x;
    if (idx >= N_NODES * H4) return;
    const int v = idx / H4;
    const int c = idx - v * H4;
    float4 s = make_float4(0.f, 0.f, 0.f, 0.f);
    #pragma unroll
    for (int k = 0; k < MAX_NB; k++) {
        const int e = __ldg(&n2e[v * MAX_NB + k]);
        if (SRC == 0) {
            const float4 gg = __ldg(&((const float4*)g_G)[e * H4 + c]);
            s.x += gg.x; s.y += gg.y; s.z += gg.z; s.w += gg.w;
        } else {
            const size_t off = (size_t)e * MPAD + c * 4;
            const uint2 uh = *(const uint2*)&g_msgh[off];
            const uint2 ul = *(const uint2*)&g_msgl[off];
            const float2 h0 = __bfloat1622float2(*(const __nv_bfloat162*)&uh.x);
            const float2 h1 = __bfloat1622float2(*(const __nv_bfloat162*)&uh.y);
            const float2 l0 = __bfloat1622float2(*(const __nv_bfloat162*)&ul.x);
            const float2 l1 = __bfloat1622float2(*(const __nv_bfloat162*)&ul.y);
            s.x += h0.x + l0.x; s.y += h0.y + l0.y;
            s.z += h1.x + l1.x; s.w += h1.y + l1.y;
        }
    }
    ((float4*)g_S)[idx] = s;
}

// -------- msg[e] = relu(inp[e] + S[e2n[e]] - G[rev[e]])  (write bf16 hi/lo) ---
__global__ void edge_update_k(const int* __restrict__ e2n,
                              const int* __restrict__ e2rev)
{
    const int idx = blockIdx.x * blockDim.x + threadIdx.x;
    if (idx >= N_EDGES * H4) return;
    const int e = idx / H4;
    const int c = idx - e * H4;
    const int v   = __ldg(&e2n[e]);
    const int rev = __ldg(&e2rev[e]);
    const float4 pi = ((const float4*)g_inp)[idx];
    const float4 ps = __ldg(&((const float4*)g_S)[v * H4 + c]);
    const float4 pg = __ldg(&((const float4*)g_G)[rev * H4 + c]);
    float m[4];
    m[0] = fmaxf(pi.x + ps.x - pg.x, 0.f);
    m[1] = fmaxf(pi.y + ps.y - pg.y, 0.f);
    m[2] = fmaxf(pi.z + ps.z - pg.z, 0.f);
    m[3] = fmaxf(pi.w + ps.w - pg.w, 0.f);
    __nv_bfloat16 h[4], l[4];
    #pragma unroll
    for (int j = 0; j < 4; j++) bsplit(m[j], h[j], l[j]);
    const size_t off = (size_t)e * MPAD + c * 4;
    *(uint2*)&g_msgh[off] = *(const uint2*)h;
    *(uint2*)&g_msgl[off] = *(const uint2*)l;
}

// ---------------- init / count / divide ---------------------------------------
__global__ void zero_out_k(float* __restrict__ out)
{
    const int i = blockIdx.x * blockDim.x + threadIdx.x;
    if (i < N_MOLS * HIDDEN) out[i] = 0.f;
    if (i < N_MOLS) g_cnt[i] = 0;
}

__global__ void count_k(const int* __restrict__ mol_ids)
{
    const int v = blockIdx.x * blockDim.x + threadIdx.x;
    if (v < N_NODES) atomicAdd(&g_cnt[mol_ids[v]], 1);
}

__global__ void divide_k(float* __restrict__ out)
{
    const int i = blockIdx.x * blockDim.x + threadIdx.x;
    if (i >= N_MOLS * HIDDEN) return;
    const int m = i / HIDDEN;
    const int c = g_cnt[m];
    out[i] = (c > 0) ? out[i] / (float)c : 0.f;
}

// ------------------------------------------------------------------------------
extern "C" void kernel_launch(void* const* d_in, const int* in_sizes, int n_in,
                              void* d_out, int out_size)
{
    const float* f_nodes = (const float*)d_in[0];
    const float* f_edges = (const float*)d_in[1];
    const float* W_i     = (const float*)d_in[2];
    const float* W_h     = (const float*)d_in[3];
    const float* W_o     = (const float*)d_in[4];
    const float* b_o     = (const float*)d_in[5];
    const int*   n2e     = (const int*)d_in[6];
    const int*   e2n     = (const int*)d_in[7];
    const int*   e2rev   = (const int*)d_in[8];
    const int*   mol_ids = (const int*)d_in[9];
    float* out = (float*)d_out;

    cudaFuncSetAttribute(mma_gemm_k<0, 10, MPAD>,
                         cudaFuncAttributeMaxDynamicSharedMemorySize, SMEM_BYTES);
    cudaFuncSetAttribute(mma_gemm_k<1, 5, FEPAD>,
                         cudaFuncAttributeMaxDynamicSharedMemorySize, SMEM_BYTES);
    cudaFuncSetAttribute(mma_gemm_k<2, 14, CATPAD>,
                         cudaFuncAttributeMaxDynamicSharedMemorySize, SMEM_BYTES);

    zero_out_k<<<(N_MOLS * HIDDEN + 255) / 256, 256>>>(out);
    count_k<<<(N_NODES + 255) / 256, 256>>>(mol_ids);
    split_W_k<HIDDEN, MPAD>  <<<(MPAD * MPAD   + 255) / 256, 256>>>(W_h);
    split_W_k<EDGE_FDIM, FEPAD><<<(MPAD * FEPAD + 255) / 256, 256>>>(W_i);
    split_W_k<NODE_FDIM + HIDDEN, CATPAD><<<(MPAD * CATPAD + 255) / 256, 256>>>(W_o);
    split_fe_k<<<(N_EDGES * FEPAD + 255) / 256, 256>>>(f_edges);
    pad_msg_k<<<(N_EDGES * (MPAD - HIDDEN) + 255) / 256, 256>>>();

    const dim3 gridE(MPAD / BN, N_EDGES / BM);   // (5, 800)
    const dim3 gridN(MPAD / BN, N_NODES / BM);   // (5, 400)

    // inp = f_edges @ W_i ; msg = relu(inp) split bf16 (tensor cores)
    mma_gemm_k<1, 5, FEPAD><<<gridE, 256, SMEM_BYTES>>>(nullptr, nullptr, nullptr);

    const int aggBlocks  = (N_NODES * H4 + 255) / 256;
    const int edgeBlocks = (N_EDGES * H4 + 255) / 256;

    for (int it = 0; it < DEPTH - 1; it++) {
        // G = msg @ W_h (tensor cores, cp.async pipelined)
        mma_gemm_k<0, 10, MPAD><<<gridE, 256, SMEM_BYTES>>>(nullptr, nullptr, nullptr);
        // S[v] = sum_k G[n2e[v,k]]
        node_agg_k<0><<<aggBlocks, 256>>>(n2e);
        // msg[e] = relu(inp[e] + S[e2n[e]] - G[rev[e]]) -> bf16 hi/lo
        edge_update_k<<<edgeBlocks, 256>>>(e2n, e2rev);
    }

    // final neighbor sum of messages into S
    node_agg_k<1><<<aggBlocks, 256>>>(n2e);

    // concat split, then out GEMM (tensor cores, atomic seg-sum epilogue)
    split_cat_k<<<(N_NODES * CATPAD + 255) / 256, 256>>>(f_nodes);
    mma_gemm_k<2, 14, CATPAD><<<gridN, 256, SMEM_BYTES>>>(b_o, mol_ids, out);

    // mean
    divide_k<<<(N_MOLS * HIDDEN + 255) / 256, 256>>>(out);
}